// round 10
// baseline (speedup 1.0000x reference)
#include <cuda_runtime.h>

// ---------------------------------------------------------------------------
// AuxSeLoss: loss = mean(bce(out0,t)) + 0.4*mean(bce(out1,t)) + 0.2*mean(bce(out2, se_t))
// se_t[b,c] = 1 if any element of targets[b] falls in histc bin c (21 bins over [0,20]).
// Shapes: out0/out1/targets [16,21,256,256] f32, out2 [16,21] f32, output scalar f32.
//
// Single fused kernel, one wave, UNIFORM work:
//   1344 groups/batch, BLK_PER_BATCH = 64 (divides 1344) -> every block does
//   exactly 21 iterations. GRID = 16*64 = 1024 < 148*7 -> one wave at the
//   7-blocks/SM residency implied by __launch_bounds__(256,7) (36-reg budget,
//   the compiler's natural allocation; R9's 32-reg squeeze starved MLP).
//   R9's 18/19-iteration imbalance (+5.5% tail) is gone.
// Per-iteration fold s += bce(out0) + 0.4*bce(out1): one accumulator, one
// partial array, half the reduction traffic.
// ---------------------------------------------------------------------------

namespace {
constexpr int   NC            = 21;
constexpr int   NB            = 16;
constexpr long long HW        = 256LL * 256LL;
constexpr long long CHW       = (long long)NC * HW;     // 1376256
constexpr long long NTOT      = (long long)NB * CHW;    // 22020096
constexpr int   V4_PER_BATCH  = (int)(CHW / 4);         // 344064
constexpr int   BLK_PER_BATCH = 64;
constexpr int   GRID          = NB * BLK_PER_BATCH;     // 1024
constexpr int   THREADS       = 256;
constexpr int   NWARP         = THREADS / 32;
constexpr int   GROUPS        = V4_PER_BATCH / THREADS; // 1344 groups of 256 v4
constexpr int   ITERS         = GROUPS / BLK_PER_BATCH; // 21, exact
static_assert(ITERS * BLK_PER_BATCH == GROUPS, "uniform work");
}

__device__ float        g_part[GRID];
__device__ unsigned int g_flagp[GRID];
__device__ unsigned int g_count;          // zero at load; reset by finalizer

__device__ __forceinline__ float bce_term(float x, float t) {
    // max(x,0) - x*t + log1p(exp(-|x|)) with HW EX2/LG2 intrinsics.
    float e = __expf(-fabsf(x));
    return fmaxf(x, 0.0f) - x * t + __logf(1.0f + e);
}

__global__ __launch_bounds__(THREADS, 7) void fused_kernel(
    const float4* __restrict__ o0,
    const float4* __restrict__ o1,
    const float4* __restrict__ tg,
    const float*  __restrict__ o2,
    float*        __restrict__ out) {

    __shared__ unsigned int flagS;
    __shared__ float redS[NWARP];
    __shared__ int   isLastS;

    const int tid  = (int)threadIdx.x;
    const int lane = tid & 31;
    const int wid  = tid >> 5;
    if (tid == 0) flagS = 0u;
    __syncthreads();

    const int blk      = (int)blockIdx.x;
    const int batch    = blk >> 6;                 // / BLK_PER_BATCH (64)
    const int bInBatch = blk & 63;
    // group g -> v4 index = batch*V4_PER_BATCH + g*THREADS + tid, g = it*64+bInBatch
    const int base = batch * V4_PER_BATCH + bInBatch * THREADS + tid;

    float s = 0.0f;
    unsigned int seen = 0u;
    const float inv_bw = 21.0f / 20.0f;   // 1 / ((n_classes-1)/n_classes)

    #pragma unroll 3
    for (int it = 0; it < ITERS; ++it) {
        const int i = base + it * (BLK_PER_BATCH * THREADS);
        float4 a  = __ldcs(&o0[i]);
        float4 b4 = __ldcs(&o1[i]);
        float4 t4 = __ldcs(&tg[i]);

        float sA = bce_term(a.x,  t4.x) + bce_term(a.y,  t4.y)
                 + bce_term(a.z,  t4.z) + bce_term(a.w,  t4.w);
        float sB = bce_term(b4.x, t4.x) + bce_term(b4.y, t4.y)
                 + bce_term(b4.z, t4.z) + bce_term(b4.w, t4.w);
        s += sA + 0.4f * sB;

        float tv[4] = {t4.x, t4.y, t4.z, t4.w};
        #pragma unroll
        for (int k = 0; k < 4; ++k) {
            float v = tv[k];
            if (v >= 0.0f && v <= 20.0f) {            // histc drops out-of-range
                int idx = min((int)(v * inv_bw), NC - 1);   // trunc == floor for v>=0
                seen |= 1u << idx;
            }
        }
    }

    #pragma unroll
    for (int off = 16; off > 0; off >>= 1) {
        s    += __shfl_down_sync(0xffffffffu, s, off);
        seen |= __shfl_down_sync(0xffffffffu, seen, off);
    }
    if (lane == 0) {
        redS[wid] = s;
        if (seen) atomicOr(&flagS, seen);
    }
    __syncthreads();

    if (tid == 0) {
        s = redS[0];
        #pragma unroll
        for (int w = 1; w < NWARP; ++w) s += redS[w];
        // L2-coherent publish (no SM ever holds these lines stale in L1)
        __stcg(&g_part[blk], s);
        __stcg(&g_flagp[blk], flagS);
        __threadfence();                               // order publishes before count
        unsigned int prev = atomicAdd(&g_count, 1u);
        isLastS = (prev == (unsigned int)(GRID - 1));
        if (isLastS) atomicExch(&g_count, 0u);         // reset for next replay
    }
    __syncthreads();
    if (!isLastS) return;

    // ---------------- last block: finalize ----------------
    __threadfence();   // acquire side of the counter handshake

    __shared__ unsigned int flagsF[NB];
    __shared__ double redD[NWARP];
    __shared__ float  redF[NWARP];
    if (tid < NB) flagsF[tid] = 0u;
    __syncthreads();

    double d01 = 0.0;
    #pragma unroll
    for (int i = tid; i < GRID; i += THREADS) {
        d01 += (double)__ldcg(&g_part[i]);
        unsigned int f = __ldcg(&g_flagp[i]);
        if (f) atomicOr(&flagsF[i >> 6], f);           // / BLK_PER_BATCH
    }
    #pragma unroll
    for (int off = 16; off > 0; off >>= 1)
        d01 += __shfl_down_sync(0xffffffffu, d01, off);
    if (lane == 0) redD[wid] = d01;
    __syncthreads();                  // also publishes flagsF

    // se BCE over ALL 336 out2 elements (strided; THREADS < 336)
    float v = 0.0f;
    for (int i = tid; i < NB * NC; i += THREADS) {
        int b = i / NC;
        int c = i - b * NC;
        float t = ((flagsF[b] >> c) & 1u) ? 1.0f : 0.0f;
        float x = o2[i];
        v += fmaxf(x, 0.0f) - x * t + log1pf(expf(-fabsf(x)));
    }
    #pragma unroll
    for (int off = 16; off > 0; off >>= 1)
        v += __shfl_down_sync(0xffffffffu, v, off);
    if (lane == 0) redF[wid] = v;
    __syncthreads();

    if (tid == 0) {
        double dd = 0.0; float vv = 0.0f;
        #pragma unroll
        for (int w = 0; w < NWARP; ++w) { dd += redD[w]; vv += redF[w]; }
        double loss01  = dd / (double)NTOT;
        double loss_se = (double)vv / (double)(NB * NC);
        out[0] = (float)(loss01 + 0.2 * loss_se);
    }
}

extern "C" void kernel_launch(void* const* d_in, const int* in_sizes, int n_in,
                              void* d_out, int out_size) {
    (void)in_sizes; (void)n_in; (void)out_size;
    const float4* o0 = (const float4*)d_in[0];
    const float4* o1 = (const float4*)d_in[1];
    const float*  o2 = (const float*) d_in[2];
    const float4* tg = (const float4*)d_in[3];

    fused_kernel<<<GRID, THREADS>>>(o0, o1, tg, o2, (float*)d_out);
}

// round 11
// speedup vs baseline: 1.0379x; 1.0379x over previous
#include <cuda_runtime.h>
#include <cstdint>

// ---------------------------------------------------------------------------
// AuxSeLoss: loss = mean(bce(out0,t)) + 0.4*mean(bce(out1,t)) + 0.2*mean(bce(out2, se_t))
// se_t[b,c] = 1 if any element of targets[b] falls in histc bin c (21 bins over [0,20]).
// Shapes: out0/out1/targets [16,21,256,256] f32, out2 [16,21] f32, output scalar f32.
//
// R9 config (GRID=1184=16x74, 256 thr, 8 blocks/SM forced via launch_bounds)
// was the best (49.4us, DRAM 69%); its limiter is register-bounded MLP: at
// 32 regs only ~6 LDG.128 fit in flight per thread. This round replaces the
// LDG stream with a cp.async.bulk (TMA-bulk) double-buffered smem pipeline:
// each iteration's data is 3 contiguous 4KB slices (o0/o1/tg), fetched by
// thread 0 into buf[stage] with an mbarrier expect_tx/complete_tx handshake
// while all 256 threads compute from the other buffer. Load depth no longer
// consumes registers. R10's lesson (148=4*37 SMs): residency quantization
// beats work quantization -- keep 1184 blocks, accept the 18/19-iter ragged
// edge (<1% per-SM skew).
// ---------------------------------------------------------------------------

namespace {
constexpr int   NC            = 21;
constexpr int   NB            = 16;
constexpr long long HW        = 256LL * 256LL;
constexpr long long CHW       = (long long)NC * HW;     // 1376256
constexpr long long NTOT      = (long long)NB * CHW;    // 22020096
constexpr int   V4_PER_BATCH  = (int)(CHW / 4);         // 344064
constexpr int   BLK_PER_BATCH = 74;
constexpr int   GRID          = NB * BLK_PER_BATCH;     // 1184 = 148*8
constexpr int   THREADS       = 256;
constexpr int   NWARP         = THREADS / 32;
constexpr int   GROUPS        = V4_PER_BATCH / THREADS; // 1344 groups of 256 v4
constexpr int   FULL_ITERS    = GROUPS / BLK_PER_BATCH; // 18
constexpr int   EXTRA_BLKS    = GROUPS % BLK_PER_BATCH; // 12
constexpr unsigned STAGE_BYTES = THREADS * 16u;         // 4096 per array
constexpr unsigned TX_BYTES    = 3u * STAGE_BYTES;      // 12288 per stage
static_assert(FULL_ITERS * BLK_PER_BATCH + EXTRA_BLKS == GROUPS, "");
}

__device__ float        g_part[GRID];
__device__ unsigned int g_flagp[GRID];
__device__ unsigned int g_count;          // zero at load; reset by finalizer

__device__ __forceinline__ float bce_term(float x, float t) {
    // max(x,0) - x*t + log1p(exp(-|x|)) with HW EX2/LG2 intrinsics.
    float e = __expf(-fabsf(x));
    return fmaxf(x, 0.0f) - x * t + __logf(1.0f + e);
}

__device__ __forceinline__ uint32_t smem_u32(const void* p) {
    uint32_t a;
    asm("{ .reg .u64 t; cvta.to.shared.u64 t, %1; cvt.u32.u64 %0, t; }"
        : "=r"(a) : "l"(p));
    return a;
}

__device__ __forceinline__ void mbar_init(uint32_t mbar, uint32_t count) {
    asm volatile("mbarrier.init.shared.b64 [%0], %1;" :: "r"(mbar), "r"(count) : "memory");
}

__device__ __forceinline__ void mbar_expect_tx(uint32_t mbar, uint32_t bytes) {
    asm volatile("mbarrier.arrive.expect_tx.shared.b64 _, [%0], %1;"
                 :: "r"(mbar), "r"(bytes) : "memory");
}

__device__ __forceinline__ void mbar_wait(uint32_t mbar, uint32_t phase) {
    asm volatile(
        "{\n\t"
        ".reg .pred P;\n\t"
        "WAIT_%=:\n\t"
        "mbarrier.try_wait.parity.acquire.cta.shared::cta.b64 P, [%0], %1, 0x989680;\n\t"
        "@!P bra WAIT_%=;\n\t"
        "}"
        :: "r"(mbar), "r"(phase) : "memory");
}

__device__ __forceinline__ void bulk_g2s(uint32_t dst_smem, const void* src, uint32_t bytes,
                                         uint32_t mbar) {
    asm volatile(
        "cp.async.bulk.shared::cluster.global.mbarrier::complete_tx::bytes "
        "[%0], [%1], %2, [%3];"
        :: "r"(dst_smem), "l"(src), "r"(bytes), "r"(mbar) : "memory");
}

__global__ __launch_bounds__(THREADS, 8) void fused_kernel(
    const float4* __restrict__ o0,
    const float4* __restrict__ o1,
    const float4* __restrict__ tg,
    const float*  __restrict__ o2,
    float*        __restrict__ out) {

    __shared__ alignas(128) float4 buf0[2][THREADS];
    __shared__ alignas(128) float4 buf1[2][THREADS];
    __shared__ alignas(128) float4 bufT[2][THREADS];
    __shared__ alignas(8)  unsigned long long mbar_store[2];
    __shared__ unsigned int flagS;
    __shared__ float redS[NWARP];
    __shared__ int   isLastS;

    const int tid  = (int)threadIdx.x;
    const int lane = tid & 31;
    const int wid  = tid >> 5;

    const uint32_t mb0 = smem_u32(&mbar_store[0]);
    const uint32_t mb1 = smem_u32(&mbar_store[1]);
    const uint32_t b0s[2] = { smem_u32(&buf0[0][0]), smem_u32(&buf0[1][0]) };
    const uint32_t b1s[2] = { smem_u32(&buf1[0][0]), smem_u32(&buf1[1][0]) };
    const uint32_t bTs[2] = { smem_u32(&bufT[0][0]), smem_u32(&bufT[1][0]) };

    if (tid == 0) {
        flagS = 0u;
        mbar_init(mb0, 1u);
        mbar_init(mb1, 1u);
    }
    __syncthreads();

    const int blk      = (int)blockIdx.x;
    const int batch    = blk / BLK_PER_BATCH;
    const int bInBatch = blk - batch * BLK_PER_BATCH;
    const int myIters  = FULL_ITERS + (bInBatch < EXTRA_BLKS ? 1 : 0);
    // stage it covers v4 range [stage_base(it), +256), contiguous:
    //   stage_base(it) = batch*V4_PER_BATCH + (it*BLK_PER_BATCH + bInBatch)*THREADS
    const int base0   = batch * V4_PER_BATCH + bInBatch * THREADS;
    const int sStride = BLK_PER_BATCH * THREADS;        // 18944 v4 per iteration

    // prologue: fill stage 0
    if (tid == 0) {
        mbar_expect_tx(mb0, TX_BYTES);
        bulk_g2s(b0s[0], o0 + base0, STAGE_BYTES, mb0);
        bulk_g2s(b1s[0], o1 + base0, STAGE_BYTES, mb0);
        bulk_g2s(bTs[0], tg + base0, STAGE_BYTES, mb0);
    }

    float s = 0.0f;
    unsigned int seen = 0u;
    const float inv_bw = 21.0f / 20.0f;   // 1 / ((n_classes-1)/n_classes)
    unsigned int phase[2] = {0u, 0u};

    for (int it = 0; it < myIters; ++it) {
        const int cur = it & 1;
        // prefetch next stage into the other buffer (consumed+synced at it-1)
        if (tid == 0 && (it + 1) < myIters) {
            const int nbase = base0 + (it + 1) * sStride;
            const uint32_t mbn = (cur ? mb0 : mb1);
            mbar_expect_tx(mbn, TX_BYTES);
            bulk_g2s(b0s[cur ^ 1], o0 + nbase, STAGE_BYTES, mbn);
            bulk_g2s(b1s[cur ^ 1], o1 + nbase, STAGE_BYTES, mbn);
            bulk_g2s(bTs[cur ^ 1], tg + nbase, STAGE_BYTES, mbn);
        }

        mbar_wait(cur ? mb1 : mb0, phase[cur]);
        phase[cur] ^= 1u;

        const float4 a  = buf0[cur][tid];
        const float4 b4 = buf1[cur][tid];
        const float4 t4 = bufT[cur][tid];

        float sA = bce_term(a.x,  t4.x) + bce_term(a.y,  t4.y)
                 + bce_term(a.z,  t4.z) + bce_term(a.w,  t4.w);
        float sB = bce_term(b4.x, t4.x) + bce_term(b4.y, t4.y)
                 + bce_term(b4.z, t4.z) + bce_term(b4.w, t4.w);
        s += sA + 0.4f * sB;

        float tv[4] = {t4.x, t4.y, t4.z, t4.w};
        #pragma unroll
        for (int k = 0; k < 4; ++k) {
            float v = tv[k];
            if (v >= 0.0f && v <= 20.0f) {            // histc drops out-of-range
                int idx = min((int)(v * inv_bw), NC - 1);   // trunc == floor for v>=0
                seen |= 1u << idx;
            }
        }
        __syncthreads();   // all reads of buf[cur] done before it is refilled at it+1
    }

    #pragma unroll
    for (int off = 16; off > 0; off >>= 1) {
        s    += __shfl_down_sync(0xffffffffu, s, off);
        seen |= __shfl_down_sync(0xffffffffu, seen, off);
    }
    if (lane == 0) {
        redS[wid] = s;
        if (seen) atomicOr(&flagS, seen);
    }
    __syncthreads();

    if (tid == 0) {
        s = redS[0];
        #pragma unroll
        for (int w = 1; w < NWARP; ++w) s += redS[w];
        // L2-coherent publish (no SM ever holds these lines stale in L1)
        __stcg(&g_part[blk], s);
        __stcg(&g_flagp[blk], flagS);
        __threadfence();                               // order publishes before count
        unsigned int prev = atomicAdd(&g_count, 1u);
        isLastS = (prev == (unsigned int)(GRID - 1));
        if (isLastS) atomicExch(&g_count, 0u);         // reset for next replay
    }
    __syncthreads();
    if (!isLastS) return;

    // ---------------- last block: finalize ----------------
    __threadfence();   // acquire side of the counter handshake

    __shared__ unsigned int flagsF[NB];
    __shared__ double redD[NWARP];
    __shared__ float  redF[NWARP];
    if (tid < NB) flagsF[tid] = 0u;
    __syncthreads();

    double d01 = 0.0;
    #pragma unroll
    for (int i = tid; i < GRID; i += THREADS) {
        d01 += (double)__ldcg(&g_part[i]);
        unsigned int f = __ldcg(&g_flagp[i]);
        if (f) atomicOr(&flagsF[i / BLK_PER_BATCH], f);
    }
    #pragma unroll
    for (int off = 16; off > 0; off >>= 1)
        d01 += __shfl_down_sync(0xffffffffu, d01, off);
    if (lane == 0) redD[wid] = d01;
    __syncthreads();                  // also publishes flagsF

    // se BCE over ALL 336 out2 elements (strided; THREADS < 336)
    float v = 0.0f;
    for (int i = tid; i < NB * NC; i += THREADS) {
        int b = i / NC;
        int c = i - b * NC;
        float t = ((flagsF[b] >> c) & 1u) ? 1.0f : 0.0f;
        float x = o2[i];
        v += fmaxf(x, 0.0f) - x * t + log1pf(expf(-fabsf(x)));
    }
    #pragma unroll
    for (int off = 16; off > 0; off >>= 1)
        v += __shfl_down_sync(0xffffffffu, v, off);
    if (lane == 0) redF[wid] = v;
    __syncthreads();

    if (tid == 0) {
        double dd = 0.0; float vv = 0.0f;
        #pragma unroll
        for (int w = 0; w < NWARP; ++w) { dd += redD[w]; vv += redF[w]; }
        double loss01  = dd / (double)NTOT;
        double loss_se = (double)vv / (double)(NB * NC);
        out[0] = (float)(loss01 + 0.2 * loss_se);
    }
}

extern "C" void kernel_launch(void* const* d_in, const int* in_sizes, int n_in,
                              void* d_out, int out_size) {
    (void)in_sizes; (void)n_in; (void)out_size;
    const float4* o0 = (const float4*)d_in[0];
    const float4* o1 = (const float4*)d_in[1];
    const float*  o2 = (const float*) d_in[2];
    const float4* tg = (const float4*)d_in[3];

    fused_kernel<<<GRID, THREADS>>>(o0, o1, tg, o2, (float*)d_out);
}

// round 12
// speedup vs baseline: 1.2013x; 1.1575x over previous
#include <cuda_runtime.h>

// ---------------------------------------------------------------------------
// AuxSeLoss: loss = mean(bce(out0,t)) + 0.4*mean(bce(out1,t)) + 0.2*mean(bce(out2, se_t))
// se_t[b,c] = 1 if any element of targets[b] falls in histc bin c (21 bins over [0,20]).
// Shapes: out0/out1/targets [16,21,256,256] f32, out2 [16,21] f32, output scalar f32.
//
// Base = R9 (best: 49.4us, DRAM 69%, occ 98%): GRID=1184=16x74, 256 threads,
// __launch_bounds__(256,8) -> 32 regs -> exactly one resident wave.
// R11 lesson: the TMA double-buffer pipeline was a downgrade (tma 3.3%, DRAM
// 59%) -- 64 warps of plain LDG.128 already provide ample MLP. Reverted.
// This round fixes R9's two measured leaks:
//  1) Ragged-edge rotation: extra-iteration blocks (12 per batch) previously
//     all had bInBatch<12 and landed on ~24 SM slots mod 148 (+5.5% tail on
//     those SMs). Effective index e=(bInBatch+batch*9)%74 spreads them.
//  2) Instruction diet: accumulate linear and log2 parts separately and
//     apply ln2 once after the loop; exp(-|x|) = EX2(|x| * -log2e) with the
//     |x| modifier folded into an imm-form FMUL. ~10 fewer FMUL per iter.
// ---------------------------------------------------------------------------

namespace {
constexpr int   NC            = 21;
constexpr int   NB            = 16;
constexpr long long HW        = 256LL * 256LL;
constexpr long long CHW       = (long long)NC * HW;     // 1376256
constexpr long long NTOT      = (long long)NB * CHW;    // 22020096
constexpr int   V4_PER_BATCH  = (int)(CHW / 4);         // 344064
constexpr int   BLK_PER_BATCH = 74;
constexpr int   GRID          = NB * BLK_PER_BATCH;     // 1184 = 148*8
constexpr int   THREADS       = 256;
constexpr int   NWARP         = THREADS / 32;
constexpr int   GROUPS        = V4_PER_BATCH / THREADS; // 1344 groups of 256 v4
constexpr int   FULL_ITERS    = GROUPS / BLK_PER_BATCH; // 18
constexpr int   EXTRA_BLKS    = GROUPS % BLK_PER_BATCH; // 12
static_assert(FULL_ITERS * BLK_PER_BATCH + EXTRA_BLKS == GROUPS, "");
constexpr float LOG2E         = 1.44269504088896340736f;
constexpr float LN2           = 0.69314718055994530942f;
}

__device__ float        g_part[GRID];
__device__ unsigned int g_flagp[GRID];
__device__ unsigned int g_count;          // zero at load; reset by finalizer

// Accumulate w * bce(x,t) split into linear part and log2 part:
//   bce = max(x,0) - x*t + ln2 * log2(1 + exp2(-|x|*log2e))
__device__ __forceinline__ void bce_acc(float x, float t, float& lin, float& lg) {
    float e = exp2f(fabsf(x) * -LOG2E);          // FMUL(|x|,imm) + MUFU.EX2
    lin += fmaxf(x, 0.0f) - x * t;
    lg  += __log2f(1.0f + e);                    // FADD + MUFU.LG2 (no ln2 FMUL)
}

__global__ __launch_bounds__(THREADS, 8) void fused_kernel(
    const float4* __restrict__ o0,
    const float4* __restrict__ o1,
    const float4* __restrict__ tg,
    const float*  __restrict__ o2,
    float*        __restrict__ out) {

    __shared__ unsigned int flagS;
    __shared__ float redS[NWARP];
    __shared__ int   isLastS;

    const int tid  = (int)threadIdx.x;
    const int lane = tid & 31;
    const int wid  = tid >> 5;
    if (tid == 0) flagS = 0u;
    __syncthreads();

    const int blk      = (int)blockIdx.x;
    const int batch    = blk / BLK_PER_BATCH;
    const int bInBatch = blk - batch * BLK_PER_BATCH;
    // Rotated effective index: permutation of [0,74) per batch; spreads the
    // 12 extra-iteration slots (e < 12) across different SMs per batch.
    const int e        = (bInBatch + batch * 9) % BLK_PER_BATCH;
    const int myIters  = FULL_ITERS + (e < EXTRA_BLKS ? 1 : 0);
    const int base     = batch * V4_PER_BATCH + e * THREADS + tid;
    const int sStride  = BLK_PER_BATCH * THREADS;

    float lin0 = 0.0f, lg0 = 0.0f;   // out0 parts
    float lin1 = 0.0f, lg1 = 0.0f;   // out1 parts
    unsigned int seen = 0u;
    const float inv_bw = 21.0f / 20.0f;   // 1 / ((n_classes-1)/n_classes)

    #pragma unroll 2
    for (int it = 0; it < myIters; ++it) {
        const int i = base + it * sStride;
        float4 a  = __ldcs(&o0[i]);
        float4 b4 = __ldcs(&o1[i]);
        float4 t4 = __ldcs(&tg[i]);

        bce_acc(a.x,  t4.x, lin0, lg0);
        bce_acc(a.y,  t4.y, lin0, lg0);
        bce_acc(a.z,  t4.z, lin0, lg0);
        bce_acc(a.w,  t4.w, lin0, lg0);
        bce_acc(b4.x, t4.x, lin1, lg1);
        bce_acc(b4.y, t4.y, lin1, lg1);
        bce_acc(b4.z, t4.z, lin1, lg1);
        bce_acc(b4.w, t4.w, lin1, lg1);

        float tv[4] = {t4.x, t4.y, t4.z, t4.w};
        #pragma unroll
        for (int k = 0; k < 4; ++k) {
            float v = tv[k];
            if (v >= 0.0f && v <= 20.0f) {            // histc drops out-of-range
                int idx = min((int)(v * inv_bw), NC - 1);   // trunc == floor for v>=0
                seen |= 1u << idx;
            }
        }
    }

    // s = bce0 + 0.4*bce1, with ln2 applied once to the log2 accumulators.
    float s = (lin0 + 0.4f * lin1) + LN2 * (lg0 + 0.4f * lg1);

    #pragma unroll
    for (int off = 16; off > 0; off >>= 1) {
        s    += __shfl_down_sync(0xffffffffu, s, off);
        seen |= __shfl_down_sync(0xffffffffu, seen, off);
    }
    if (lane == 0) {
        redS[wid] = s;
        if (seen) atomicOr(&flagS, seen);
    }
    __syncthreads();

    if (tid == 0) {
        s = redS[0];
        #pragma unroll
        for (int w = 1; w < NWARP; ++w) s += redS[w];
        // L2-coherent publish (no SM ever holds these lines stale in L1)
        __stcg(&g_part[blk], s);
        __stcg(&g_flagp[blk], flagS);
        __threadfence();                               // order publishes before count
        unsigned int prev = atomicAdd(&g_count, 1u);
        isLastS = (prev == (unsigned int)(GRID - 1));
        if (isLastS) atomicExch(&g_count, 0u);         // reset for next replay
    }
    __syncthreads();
    if (!isLastS) return;

    // ---------------- last block: finalize ----------------
    __threadfence();   // acquire side of the counter handshake

    __shared__ unsigned int flagsF[NB];
    __shared__ double redD[NWARP];
    __shared__ float  redF[NWARP];
    if (tid < NB) flagsF[tid] = 0u;
    __syncthreads();

    double d01 = 0.0;
    #pragma unroll
    for (int i = tid; i < GRID; i += THREADS) {
        d01 += (double)__ldcg(&g_part[i]);
        unsigned int f = __ldcg(&g_flagp[i]);
        if (f) atomicOr(&flagsF[i / BLK_PER_BATCH], f);
    }
    #pragma unroll
    for (int off = 16; off > 0; off >>= 1)
        d01 += __shfl_down_sync(0xffffffffu, d01, off);
    if (lane == 0) redD[wid] = d01;
    __syncthreads();                  // also publishes flagsF

    // se BCE over ALL 336 out2 elements (strided; THREADS < 336)
    float v = 0.0f;
    for (int i = tid; i < NB * NC; i += THREADS) {
        int b = i / NC;
        int c = i - b * NC;
        float t = ((flagsF[b] >> c) & 1u) ? 1.0f : 0.0f;
        float x = o2[i];
        v += fmaxf(x, 0.0f) - x * t + log1pf(expf(-fabsf(x)));
    }
    #pragma unroll
    for (int off = 16; off > 0; off >>= 1)
        v += __shfl_down_sync(0xffffffffu, v, off);
    if (lane == 0) redF[wid] = v;
    __syncthreads();

    if (tid == 0) {
        double dd = 0.0; float vv = 0.0f;
        #pragma unroll
        for (int w = 0; w < NWARP; ++w) { dd += redD[w]; vv += redF[w]; }
        double loss01  = dd / (double)NTOT;
        double loss_se = (double)vv / (double)(NB * NC);
        out[0] = (float)(loss01 + 0.2 * loss_se);
    }
}

extern "C" void kernel_launch(void* const* d_in, const int* in_sizes, int n_in,
                              void* d_out, int out_size) {
    (void)in_sizes; (void)n_in; (void)out_size;
    const float4* o0 = (const float4*)d_in[0];
    const float4* o1 = (const float4*)d_in[1];
    const float*  o2 = (const float*) d_in[2];
    const float4* tg = (const float4*)d_in[3];

    fused_kernel<<<GRID, THREADS>>>(o0, o1, tg, o2, (float*)d_out);
}

// round 13
// speedup vs baseline: 1.2086x; 1.0060x over previous
#include <cuda_runtime.h>

// ---------------------------------------------------------------------------
// AuxSeLoss: loss = mean(bce(out0,t)) + 0.4*mean(bce(out1,t)) + 0.2*mean(bce(out2, se_t))
// se_t[b,c] = 1 if any element of targets[b] falls in histc bin c (21 bins over [0,20]).
// Shapes: out0/out1/targets [16,21,256,256] f32, out2 [16,21] f32, output scalar f32.
//
// Base = R12 (best: 48.2us, DRAM 71.7%, occ 97.3%): GRID=1184=16x74,
// 256 threads, __launch_bounds__(256,8), ragged-edge rotation, lin/log split.
// R13 change -- logarithm fusion: sum of log2(1+e_i) = log2(prod (1+e_i)).
// Four (1+e) factors per tensor per iteration (each in (1,2], product <= 16,
// f32-exact range) are combined with FFMA (p = p*(1+e) = fma(p,e,p)) and a
// SINGLE LG2 replaces four. MUFU per iter: 16 -> 10 (8 EX2 + 2 LG2), cutting
// MUFU-pipe occupancy ~44% -> ~28% and freeing issue slots for the LDG stream.
// ---------------------------------------------------------------------------

namespace {
constexpr int   NC            = 21;
constexpr int   NB            = 16;
constexpr long long HW        = 256LL * 256LL;
constexpr long long CHW       = (long long)NC * HW;     // 1376256
constexpr long long NTOT      = (long long)NB * CHW;    // 22020096
constexpr int   V4_PER_BATCH  = (int)(CHW / 4);         // 344064
constexpr int   BLK_PER_BATCH = 74;
constexpr int   GRID          = NB * BLK_PER_BATCH;     // 1184 = 148*8
constexpr int   THREADS       = 256;
constexpr int   NWARP         = THREADS / 32;
constexpr int   GROUPS        = V4_PER_BATCH / THREADS; // 1344 groups of 256 v4
constexpr int   FULL_ITERS    = GROUPS / BLK_PER_BATCH; // 18
constexpr int   EXTRA_BLKS    = GROUPS % BLK_PER_BATCH; // 12
static_assert(FULL_ITERS * BLK_PER_BATCH + EXTRA_BLKS == GROUPS, "");
constexpr float LOG2E         = 1.44269504088896340736f;
constexpr float LN2           = 0.69314718055994530942f;
}

__device__ float        g_part[GRID];
__device__ unsigned int g_flagp[GRID];
__device__ unsigned int g_count;          // zero at load; reset by finalizer

__global__ __launch_bounds__(THREADS, 8) void fused_kernel(
    const float4* __restrict__ o0,
    const float4* __restrict__ o1,
    const float4* __restrict__ tg,
    const float*  __restrict__ o2,
    float*        __restrict__ out) {

    __shared__ unsigned int flagS;
    __shared__ float redS[NWARP];
    __shared__ int   isLastS;

    const int tid  = (int)threadIdx.x;
    const int lane = tid & 31;
    const int wid  = tid >> 5;
    if (tid == 0) flagS = 0u;
    __syncthreads();

    const int blk      = (int)blockIdx.x;
    const int batch    = blk / BLK_PER_BATCH;
    const int bInBatch = blk - batch * BLK_PER_BATCH;
    // Rotated effective index: permutation of [0,74) per batch; spreads the
    // 12 extra-iteration slots (e < 12) across different SMs per batch.
    const int eIdx     = (bInBatch + batch * 9) % BLK_PER_BATCH;
    const int myIters  = FULL_ITERS + (eIdx < EXTRA_BLKS ? 1 : 0);
    const int base     = batch * V4_PER_BATCH + eIdx * THREADS + tid;
    const int sStride  = BLK_PER_BATCH * THREADS;

    float lin0 = 0.0f, lg0 = 0.0f;   // out0: linear part, log2 part
    float lin1 = 0.0f, lg1 = 0.0f;   // out1
    unsigned int seen = 0u;
    const float inv_bw = 21.0f / 20.0f;   // 1 / ((n_classes-1)/n_classes)

    #pragma unroll 2
    for (int it = 0; it < myIters; ++it) {
        const int i = base + it * sStride;
        float4 a  = __ldcs(&o0[i]);
        float4 b4 = __ldcs(&o1[i]);
        float4 t4 = __ldcs(&tg[i]);

        // --- out0: product of (1+exp(-|x|)) factors, one LG2 per iteration ---
        {
            float e, p;
            e = exp2f(fabsf(a.x) * -LOG2E); p = 1.0f + e;
            e = exp2f(fabsf(a.y) * -LOG2E); p = fmaf(p, e, p);
            e = exp2f(fabsf(a.z) * -LOG2E); p = fmaf(p, e, p);
            e = exp2f(fabsf(a.w) * -LOG2E); p = fmaf(p, e, p);
            lg0 += __log2f(p);
            lin0 += (fmaxf(a.x, 0.0f) - a.x * t4.x)
                  + (fmaxf(a.y, 0.0f) - a.y * t4.y)
                  + (fmaxf(a.z, 0.0f) - a.z * t4.z)
                  + (fmaxf(a.w, 0.0f) - a.w * t4.w);
        }
        // --- out1 ---
        {
            float e, p;
            e = exp2f(fabsf(b4.x) * -LOG2E); p = 1.0f + e;
            e = exp2f(fabsf(b4.y) * -LOG2E); p = fmaf(p, e, p);
            e = exp2f(fabsf(b4.z) * -LOG2E); p = fmaf(p, e, p);
            e = exp2f(fabsf(b4.w) * -LOG2E); p = fmaf(p, e, p);
            lg1 += __log2f(p);
            lin1 += (fmaxf(b4.x, 0.0f) - b4.x * t4.x)
                  + (fmaxf(b4.y, 0.0f) - b4.y * t4.y)
                  + (fmaxf(b4.z, 0.0f) - b4.z * t4.z)
                  + (fmaxf(b4.w, 0.0f) - b4.w * t4.w);
        }

        float tv[4] = {t4.x, t4.y, t4.z, t4.w};
        #pragma unroll
        for (int k = 0; k < 4; ++k) {
            float v = tv[k];
            if (v >= 0.0f && v <= 20.0f) {            // histc drops out-of-range
                int idx = min((int)(v * inv_bw), NC - 1);   // trunc == floor for v>=0
                seen |= 1u << idx;
            }
        }
    }

    // s = bce0 + 0.4*bce1, with ln2 applied once to the log2 accumulators.
    float s = (lin0 + 0.4f * lin1) + LN2 * (lg0 + 0.4f * lg1);

    #pragma unroll
    for (int off = 16; off > 0; off >>= 1) {
        s    += __shfl_down_sync(0xffffffffu, s, off);
        seen |= __shfl_down_sync(0xffffffffu, seen, off);
    }
    if (lane == 0) {
        redS[wid] = s;
        if (seen) atomicOr(&flagS, seen);
    }
    __syncthreads();

    if (tid == 0) {
        s = redS[0];
        #pragma unroll
        for (int w = 1; w < NWARP; ++w) s += redS[w];
        // L2-coherent publish (no SM ever holds these lines stale in L1)
        __stcg(&g_part[blk], s);
        __stcg(&g_flagp[blk], flagS);
        __threadfence();                               // order publishes before count
        unsigned int prev = atomicAdd(&g_count, 1u);
        isLastS = (prev == (unsigned int)(GRID - 1));
        if (isLastS) atomicExch(&g_count, 0u);         // reset for next replay
    }
    __syncthreads();
    if (!isLastS) return;

    // ---------------- last block: finalize ----------------
    __threadfence();   // acquire side of the counter handshake

    __shared__ unsigned int flagsF[NB];
    __shared__ double redD[NWARP];
    __shared__ float  redF[NWARP];
    if (tid < NB) flagsF[tid] = 0u;
    __syncthreads();

    double d01 = 0.0;
    #pragma unroll
    for (int i = tid; i < GRID; i += THREADS) {
        d01 += (double)__ldcg(&g_part[i]);
        unsigned int f = __ldcg(&g_flagp[i]);
        if (f) atomicOr(&flagsF[i / BLK_PER_BATCH], f);
    }
    #pragma unroll
    for (int off = 16; off > 0; off >>= 1)
        d01 += __shfl_down_sync(0xffffffffu, d01, off);
    if (lane == 0) redD[wid] = d01;
    __syncthreads();                  // also publishes flagsF

    // se BCE over ALL 336 out2 elements (strided; THREADS < 336)
    float v = 0.0f;
    for (int i = tid; i < NB * NC; i += THREADS) {
        int b = i / NC;
        int c = i - b * NC;
        float t = ((flagsF[b] >> c) & 1u) ? 1.0f : 0.0f;
        float x = o2[i];
        v += fmaxf(x, 0.0f) - x * t + log1pf(expf(-fabsf(x)));
    }
    #pragma unroll
    for (int off = 16; off > 0; off >>= 1)
        v += __shfl_down_sync(0xffffffffu, v, off);
    if (lane == 0) redF[wid] = v;
    __syncthreads();

    if (tid == 0) {
        double dd = 0.0; float vv = 0.0f;
        #pragma unroll
        for (int w = 0; w < NWARP; ++w) { dd += redD[w]; vv += redF[w]; }
        double loss01  = dd / (double)NTOT;
        double loss_se = (double)vv / (double)(NB * NC);
        out[0] = (float)(loss01 + 0.2 * loss_se);
    }
}

extern "C" void kernel_launch(void* const* d_in, const int* in_sizes, int n_in,
                              void* d_out, int out_size) {
    (void)in_sizes; (void)n_in; (void)out_size;
    const float4* o0 = (const float4*)d_in[0];
    const float4* o1 = (const float4*)d_in[1];
    const float*  o2 = (const float*) d_in[2];
    const float4* tg = (const float4*)d_in[3];

    fused_kernel<<<GRID, THREADS>>>(o0, o1, tg, o2, (float*)d_out);
}